// round 1
// baseline (speedup 1.0000x reference)
#include <cuda_runtime.h>
#include <cuda_bf16.h>

#define H 2048
#define HV4 (H / 4)
#define NTHREADS 256

// Persistent scratch (statically allocated __device__ globals — allowed)
__device__ float g_Wc[4 * H * H];   // combined W_ih + W_hh, 64 MB
__device__ float g_bc[4 * H];       // combined bias
__device__ float g_hbuf[2][H];      // double-buffered hidden state
__device__ int   g_ctr;             // barrier counter

// ---------------------------------------------------------------------------
// Prologue: Wc = W_ih + W_hh, bc = b_ih + b_hh, hbuf[0] = inputs[0], ctr = 0
// ---------------------------------------------------------------------------
__global__ void lstm_prologue(const float* __restrict__ inputs,
                              const float* __restrict__ W_ih,
                              const float* __restrict__ W_hh,
                              const float* __restrict__ b_ih,
                              const float* __restrict__ b_hh) {
    const long long idx    = (long long)blockIdx.x * blockDim.x + threadIdx.x;
    const long long stride = (long long)gridDim.x * blockDim.x;
    const float4* a4 = (const float4*)W_ih;
    const float4* b4 = (const float4*)W_hh;
    float4* w4 = (float4*)g_Wc;
    const long long n4 = (long long)4 * H * H / 4;
    for (long long i = idx; i < n4; i += stride) {
        float4 a = a4[i], b = b4[i];
        w4[i] = make_float4(a.x + b.x, a.y + b.y, a.z + b.z, a.w + b.w);
    }
    if (idx < 4 * H) g_bc[idx] = b_ih[idx] + b_hh[idx];
    if (idx < H)     g_hbuf[0][idx] = inputs[idx];   // x0 = inputs row 0
    if (idx == 0)    g_ctr = 0;
}

__device__ __forceinline__ float sigmoidf_fast(float x) {
    return 1.0f / (1.0f + __expf(-x));
}

// ---------------------------------------------------------------------------
// Persistent LSTM kernel: grid = #SMs (one co-resident wave), global barrier
// per step via monotonic atomic counter.
// ---------------------------------------------------------------------------
__global__ void __launch_bounds__(NTHREADS, 1)
lstm_main(const float* __restrict__ W_ih,
          const float* __restrict__ W_out,
          const float* __restrict__ b_out,
          const int*   __restrict__ steps_ptr,
          float*       __restrict__ out) {
    __shared__ float sh_h[H];            // 8 KB: current hidden vector
    __shared__ float sh_g[128];          // gate pre-activations (nk*4 <= 64)
    __shared__ float sh_c[32];           // block-private cell state
    __shared__ float sh_logits[16];

    const int tid  = threadIdx.x;
    const int warp = tid >> 5;
    const int lane = tid & 31;
    const int nb   = gridDim.x;
    const int bid  = blockIdx.x;

    // Partition h indices [k0, k1) to this block
    const int k0 = (int)(((long long)bid * H) / nb);
    const int k1 = (int)(((long long)(bid + 1) * H) / nb);
    const int nk = k1 - k0;
    const int nrows = nk * 4;

    const int steps = steps_ptr ? steps_ptr[0] : 512;

    if (tid < nk) sh_c[tid] = 0.0f;

    float4* sh_h4 = (float4*)sh_h;

    for (int s = 0; s < steps; ++s) {
        const float* W   = (s == 0) ? W_ih : g_Wc;
        const float* hin = g_hbuf[s & 1];

        // Load the full hidden vector into smem, bypassing L1 (other SMs
        // wrote it last step; L1 lines may be stale).
        const float4* hin4 = (const float4*)hin;
        for (int i = tid; i < HV4; i += NTHREADS)
            sh_h4[i] = __ldcg(hin4 + i);
        __syncthreads();

        // Each warp computes full dot products for its assigned gate rows.
        for (int r = warp; r < nrows; r += (NTHREADS / 32)) {
            const int klocal = r >> 2;
            const int gate   = r & 3;
            const int row    = (k0 + klocal) + gate * H;
            const float4* wrow = (const float4*)(W + (size_t)row * H);
            float acc = 0.0f;
            #pragma unroll
            for (int c = lane; c < HV4; c += 32) {
                float4 w  = __ldg(wrow + c);
                float4 hv = sh_h4[c];
                acc = fmaf(w.x, hv.x, acc);
                acc = fmaf(w.y, hv.y, acc);
                acc = fmaf(w.z, hv.z, acc);
                acc = fmaf(w.w, hv.w, acc);
            }
            #pragma unroll
            for (int o = 16; o; o >>= 1)
                acc += __shfl_xor_sync(0xffffffffu, acc, o);
            if (lane == 0)
                sh_g[klocal * 4 + gate] = acc + g_bc[row];
        }
        __syncthreads();

        // Elementwise LSTM update (block-local, fused)
        float* hout = g_hbuf[(s + 1) & 1];
        if (tid < nk) {
            const float gi = sh_g[tid * 4 + 0];
            const float gf = sh_g[tid * 4 + 1];
            const float gg = sh_g[tid * 4 + 2];
            const float go = sh_g[tid * 4 + 3];
            const float i_g = sigmoidf_fast(gi);
            const float f_g = sigmoidf_fast(gf);
            const float g_g = tanhf(gg);
            const float o_g = sigmoidf_fast(go);
            const float c_n = f_g * sh_c[tid] + i_g * g_g;
            sh_c[tid] = c_n;
            const float h_n = o_g * tanhf(c_n);
            hout[k0 + tid] = h_n;
            if (s == steps - 1) {
                out[11 + k0 + tid]     = h_n;   // h output
                out[11 + H + k0 + tid] = c_n;   // c output
            }
        }

        // Grid-wide barrier: publish writes, arrive, spin.
        __threadfence();
        __syncthreads();
        if (tid == 0) {
            atomicAdd(&g_ctr, 1);
            const int target = nb * (s + 1);
            while (*(volatile int*)&g_ctr < target)
                __nanosleep(64);
        }
        __syncthreads();
    }

    // Block 0: classification head + softmax on final h
    if (bid == 0) {
        const float4* hf4 = (const float4*)g_hbuf[steps & 1];
        for (int i = tid; i < HV4; i += NTHREADS)
            sh_h4[i] = __ldcg(hf4 + i);
        __syncthreads();
        for (int r = warp; r < 11; r += (NTHREADS / 32)) {
            const float4* wrow = (const float4*)(W_out + (size_t)r * H);
            float acc = 0.0f;
            #pragma unroll
            for (int c = lane; c < HV4; c += 32) {
                float4 w  = __ldg(wrow + c);
                float4 hv = sh_h4[c];
                acc = fmaf(w.x, hv.x, acc);
                acc = fmaf(w.y, hv.y, acc);
                acc = fmaf(w.z, hv.z, acc);
                acc = fmaf(w.w, hv.w, acc);
            }
            #pragma unroll
            for (int o = 16; o; o >>= 1)
                acc += __shfl_xor_sync(0xffffffffu, acc, o);
            if (lane == 0) sh_logits[r] = acc + __ldg(b_out + r);
        }
        __syncthreads();
        if (tid == 0) {
            float m = sh_logits[0];
            #pragma unroll
            for (int i = 1; i < 11; i++) m = fmaxf(m, sh_logits[i]);
            float e[11];
            float sum = 0.0f;
            #pragma unroll
            for (int i = 0; i < 11; i++) { e[i] = __expf(sh_logits[i] - m); sum += e[i]; }
            const float inv = 1.0f / sum;
            #pragma unroll
            for (int i = 0; i < 11; i++) out[i] = e[i] * inv;
        }
    }
}

// ---------------------------------------------------------------------------
// Launch wrapper
// ---------------------------------------------------------------------------
extern "C" void kernel_launch(void* const* d_in, const int* in_sizes, int n_in,
                              void* d_out, int out_size) {
    const float* inputs = (const float*)d_in[0];   // (512, 2048) f32
    const float* W_ih   = (const float*)d_in[1];   // (8192, 2048) f32
    const float* W_hh   = (const float*)d_in[2];   // (8192, 2048) f32
    const float* b_ih   = (const float*)d_in[3];   // (8192,) f32
    const float* b_hh   = (const float*)d_in[4];   // (8192,) f32
    const float* W_out  = (const float*)d_in[5];   // (11, 2048) f32
    const float* b_out  = (const float*)d_in[6];   // (11,) f32
    const int*   steps  = (n_in > 7) ? (const int*)d_in[7] : nullptr;
    float* out = (float*)d_out;                    // [probs(11) | h(2048) | c(2048)]

    int nsm = 148;
    cudaDeviceGetAttribute(&nsm, cudaDevAttrMultiProcessorCount, 0);

    lstm_prologue<<<4096, 256>>>(inputs, W_ih, W_hh, b_ih, b_hh);
    lstm_main<<<nsm, NTHREADS>>>(W_ih, W_out, b_out, steps, out);
}

// round 3
// speedup vs baseline: 1.3899x; 1.3899x over previous
#include <cuda_runtime.h>
#include <cuda_fp16.h>

#define H 2048
#define NTHREADS 256
#define CACHED_ROWS 52
#define SMEM_W_BYTES (CACHED_ROWS * H * 2)          // 212992 B fp16 weights
#define SMEM_H_BYTES (H * 4)                        // 8192 B fp32 hidden
#define SMEM_DYN_BYTES (SMEM_W_BYTES + SMEM_H_BYTES)

// -------- persistent device scratch (static allocation is allowed) --------
__device__ __half g_Wh[4 * H * H];   // combined W_ih+W_hh, fp16, column-permuted, 32 MB
__device__ float  g_bc[4 * H];       // b_ih + b_hh
__device__ float  g_gates0[4 * H];   // exact fp32 gates of step 0
__device__ float  g_hbuf[2][H];      // double-buffered hidden state
__device__ int    g_ctr;             // grid barrier counter

// ---------------------------------------------------------------------------
// Prologue A: Wc = fp16(W_ih + W_hh) with column permutation
//   uint4 t = r*256 + i*32 + lane ; half j inside it holds column
//   c = lane + 256*i + 32*j  -> per-lane h gathers are bank-conflict-free.
// ---------------------------------------------------------------------------
__global__ void lstm_prologue(const float* __restrict__ W_ih,
                              const float* __restrict__ W_hh,
                              const float* __restrict__ b_ih,
                              const float* __restrict__ b_hh) {
    const long long idx    = (long long)blockIdx.x * blockDim.x + threadIdx.x;
    const long long stride = (long long)gridDim.x * blockDim.x;
    const long long TOT    = (long long)4 * H * 8 * 32;   // rows * i * lane
    for (long long t = idx; t < TOT; t += stride) {
        const int l = (int)(t & 31);
        const int i = (int)((t >> 5) & 7);
        const int r = (int)(t >> 8);
        const float* wi = W_ih + (size_t)r * H;
        const float* wh = W_hh + (size_t)r * H;
        __half hv[8];
        #pragma unroll
        for (int j = 0; j < 8; j++) {
            const int c = l + 256 * i + 32 * j;
            hv[j] = __float2half(wi[c] + wh[c]);
        }
        ((uint4*)g_Wh)[t] = *(const uint4*)hv;
    }
    if (idx < 4 * H) g_bc[idx] = b_ih[idx] + b_hh[idx];
    if (idx == 0)    g_ctr = 0;
}

// ---------------------------------------------------------------------------
// Prologue B: exact fp32 step-0 gates:  gates0 = W_ih @ x0 + b_ih + b_hh
// ---------------------------------------------------------------------------
__global__ void lstm_gates0(const float* __restrict__ inputs,
                            const float* __restrict__ W_ih,
                            const float* __restrict__ b_ih,
                            const float* __restrict__ b_hh) {
    const int row  = blockIdx.x * 8 + (threadIdx.x >> 5);
    const int lane = threadIdx.x & 31;
    if (row >= 4 * H) return;
    const float4* w4 = (const float4*)(W_ih + (size_t)row * H);
    const float4* x4 = (const float4*)inputs;   // row 0 of inputs
    float acc = 0.0f;
    for (int c = lane; c < H / 4; c += 32) {
        float4 w = __ldg(w4 + c), x = __ldg(x4 + c);
        acc = fmaf(w.x, x.x, acc);
        acc = fmaf(w.y, x.y, acc);
        acc = fmaf(w.z, x.z, acc);
        acc = fmaf(w.w, x.w, acc);
    }
    #pragma unroll
    for (int o = 16; o; o >>= 1) acc += __shfl_xor_sync(0xffffffffu, acc, o);
    if (lane == 0) g_gates0[row] = acc + b_ih[row] + b_hh[row];
}

__device__ __forceinline__ float sigmoidf_fast(float x) {
    return 1.0f / (1.0f + __expf(-x));
}

// Dot of one permuted fp16 weight row with the register-resident h slice.
template <bool GLOBAL>
__device__ __forceinline__ float row_dot(const uint4* __restrict__ wr,
                                         const float (&hreg)[8][8], int lane) {
    float a0 = 0.f, a1 = 0.f, a2 = 0.f, a3 = 0.f;
    #pragma unroll
    for (int i = 0; i < 8; i++) {
        uint4 w = GLOBAL ? __ldg(wr + lane + 32 * i) : wr[lane + 32 * i];
        const __half2* wh = reinterpret_cast<const __half2*>(&w);
        const float2 f0 = __half22float2(wh[0]);
        const float2 f1 = __half22float2(wh[1]);
        const float2 f2 = __half22float2(wh[2]);
        const float2 f3 = __half22float2(wh[3]);
        a0 = fmaf(f0.x, hreg[i][0], a0);
        a1 = fmaf(f0.y, hreg[i][1], a1);
        a2 = fmaf(f1.x, hreg[i][2], a2);
        a3 = fmaf(f1.y, hreg[i][3], a3);
        a0 = fmaf(f2.x, hreg[i][4], a0);
        a1 = fmaf(f2.y, hreg[i][5], a1);
        a2 = fmaf(f3.x, hreg[i][6], a2);
        a3 = fmaf(f3.y, hreg[i][7], a3);
    }
    return (a0 + a1) + (a2 + a3);
}

// ---------------------------------------------------------------------------
// Persistent LSTM: weights live in SMEM (fp16), h in registers, fp32 accum.
// ---------------------------------------------------------------------------
__global__ void __launch_bounds__(NTHREADS, 1)
lstm_main(const float* __restrict__ W_out,
          const float* __restrict__ b_out,
          const int*   __restrict__ steps_ptr,
          float*       __restrict__ out) {
    extern __shared__ unsigned char smem_raw[];
    __half* sh_w = (__half*)smem_raw;
    float*  sh_h = (float*)(smem_raw + SMEM_W_BYTES);
    __shared__ float sh_g[128];
    __shared__ float sh_b[128];
    __shared__ float sh_c[64];
    __shared__ float sh_logits[16];

    const int tid  = threadIdx.x;
    const int warp = tid >> 5;
    const int lane = tid & 31;
    const int nb   = gridDim.x;
    const int bid  = blockIdx.x;

    const int k0 = (int)(((long long)bid * H) / nb);
    const int k1 = (int)(((long long)(bid + 1) * H) / nb);
    const int nk = k1 - k0;
    const int nrows = nk * 4;
    const int cached = nrows < CACHED_ROWS ? nrows : CACHED_ROWS;
    const int steps = steps_ptr ? steps_ptr[0] : 512;

    // --- one-time prefill: cached weight rows, biases, cell state ---
    {
        const uint4* gW4 = (const uint4*)g_Wh;
        uint4* sW4 = (uint4*)sh_w;
        const int tot = cached * (H / 8);              // 256 uint4 per row
        for (int idx = tid; idx < tot; idx += NTHREADS) {
            const int lr  = idx >> 8;
            const int pos = idx & 255;
            const int grow = (lr & 3) * H + k0 + (lr >> 2);
            sW4[lr * 256 + pos] = __ldg(gW4 + (size_t)grow * 256 + pos);
        }
        if (tid < nrows) sh_b[tid] = g_bc[(tid & 3) * H + k0 + (tid >> 2)];
        for (int k = tid; k < nk; k += NTHREADS) sh_c[k] = 0.0f;
    }
    __syncthreads();

    for (int s = 0; s < steps; ++s) {
        if (s == 0) {
            if (tid < nrows)
                sh_g[tid] = g_gates0[(tid & 3) * H + k0 + (tid >> 2)];
            __syncthreads();
        } else {
            // stage h (written by all blocks last step) into smem, L1-bypassing
            const float4* hin4 = (const float4*)g_hbuf[s & 1];
            for (int i = tid; i < H / 4; i += NTHREADS)
                ((float4*)sh_h)[i] = __ldcg(hin4 + i);
            __syncthreads();

            // per-lane h slice -> registers (conflict-free: bank == lane)
            float hreg[8][8];
            #pragma unroll
            for (int i = 0; i < 8; i++)
                #pragma unroll
                for (int j = 0; j < 8; j++)
                    hreg[i][j] = sh_h[lane + 256 * i + 32 * j];

            for (int r = warp; r < nrows; r += NTHREADS / 32) {
                float acc;
                if (r < cached) {
                    acc = row_dot<false>((const uint4*)(sh_w + (size_t)r * H), hreg, lane);
                } else {
                    const size_t grow = (size_t)((r & 3) * H + k0 + (r >> 2));
                    acc = row_dot<true>(((const uint4*)g_Wh) + grow * (H / 8), hreg, lane);
                }
                #pragma unroll
                for (int o = 16; o; o >>= 1)
                    acc += __shfl_xor_sync(0xffffffffu, acc, o);
                if (lane == 0) sh_g[r] = acc + sh_b[r];
            }
            __syncthreads();
        }

        // elementwise LSTM update (block-local)
        float* hout = g_hbuf[(s + 1) & 1];
        for (int k = tid; k < nk; k += NTHREADS) {
            const float i_g = sigmoidf_fast(sh_g[k * 4 + 0]);
            const float f_g = sigmoidf_fast(sh_g[k * 4 + 1]);
            const float g_g = tanhf(sh_g[k * 4 + 2]);
            const float o_g = sigmoidf_fast(sh_g[k * 4 + 3]);
            const float c_n = f_g * sh_c[k] + i_g * g_g;
            sh_c[k] = c_n;
            const float h_n = o_g * tanhf(c_n);
            hout[k0 + k] = h_n;
            if (s == steps - 1) {
                out[11 + k0 + k]     = h_n;
                out[11 + H + k0 + k] = c_n;
            }
        }

        // grid barrier (bounded polling via nanosleep)
        __threadfence();
        __syncthreads();
        if (tid == 0) {
            atomicAdd(&g_ctr, 1);
            const int target = nb * (s + 1);
            while (*(volatile int*)&g_ctr < target)
                __nanosleep(64);
            __threadfence();
        }
        __syncthreads();
    }

    // classification head + softmax (block 0)
    if (bid == 0) {
        const float4* hf4 = (const float4*)g_hbuf[steps & 1];
        for (int i = tid; i < H / 4; i += NTHREADS)
            ((float4*)sh_h)[i] = __ldcg(hf4 + i);
        __syncthreads();
        for (int r = warp; r < 11; r += NTHREADS / 32) {
            const float4* wrow = (const float4*)(W_out + (size_t)r * H);
            float acc = 0.0f;
            for (int c = lane; c < H / 4; c += 32) {
                float4 w  = __ldg(wrow + c);
                float4 hv = ((float4*)sh_h)[c];
                acc = fmaf(w.x, hv.x, acc);
                acc = fmaf(w.y, hv.y, acc);
                acc = fmaf(w.z, hv.z, acc);
                acc = fmaf(w.w, hv.w, acc);
            }
            #pragma unroll
            for (int o = 16; o; o >>= 1)
                acc += __shfl_xor_sync(0xffffffffu, acc, o);
            if (lane == 0) sh_logits[r] = acc + __ldg(b_out + r);
        }
        __syncthreads();
        if (tid == 0) {
            float m = sh_logits[0];
            #pragma unroll
            for (int i = 1; i < 11; i++) m = fmaxf(m, sh_logits[i]);
            float e[11], sum = 0.0f;
            #pragma unroll
            for (int i = 0; i < 11; i++) { e[i] = __expf(sh_logits[i] - m); sum += e[i]; }
            const float inv = 1.0f / sum;
            #pragma unroll
            for (int i = 0; i < 11; i++) out[i] = e[i] * inv;
        }
    }
}

// ---------------------------------------------------------------------------
extern "C" void kernel_launch(void* const* d_in, const int* in_sizes, int n_in,
                              void* d_out, int out_size) {
    const float* inputs = (const float*)d_in[0];
    const float* W_ih   = (const float*)d_in[1];
    const float* W_hh   = (const float*)d_in[2];
    const float* b_ih   = (const float*)d_in[3];
    const float* b_hh   = (const float*)d_in[4];
    const float* W_out  = (const float*)d_in[5];
    const float* b_out  = (const float*)d_in[6];
    const int*   steps  = (n_in > 7) ? (const int*)d_in[7] : nullptr;
    float* out = (float*)d_out;

    int nsm = 148;
    cudaDeviceGetAttribute(&nsm, cudaDevAttrMultiProcessorCount, 0);

    cudaFuncSetAttribute(lstm_main, cudaFuncAttributeMaxDynamicSharedMemorySize,
                         SMEM_DYN_BYTES);

    lstm_prologue<<<2048, 256>>>(W_ih, W_hh, b_ih, b_hh);
    lstm_gates0<<<1024, 256>>>(inputs, W_ih, b_ih, b_hh);
    lstm_main<<<nsm, NTHREADS, SMEM_DYN_BYTES>>>(W_out, b_out, steps, out);
}

// round 4
// speedup vs baseline: 1.4685x; 1.0565x over previous
#include <cuda_runtime.h>
#include <cuda_fp16.h>

#define H 2048
#define NTHREADS 256
#define CACHED_ROWS 52
#define SMEM_W_BYTES (CACHED_ROWS * H * 2)          // 212992 B fp16 weights
#define SMEM_H_BYTES (H * 4)                        // 8192 B fp32 hidden
#define SMEM_DYN_BYTES (SMEM_W_BYTES + SMEM_H_BYTES)

// -------- persistent device scratch (static allocation is allowed) --------
__device__ __half g_Wh[4 * H * H];   // combined W_ih+W_hh, fp16, column-permuted, 32 MB
__device__ float  g_bc[4 * H];       // b_ih + b_hh
__device__ float  g_gates0[4 * H];   // exact fp32 gates of step 0
__device__ float  g_hbuf[2][H];      // double-buffered hidden state
__device__ int    g_ctr;             // grid barrier counter

// ---------------------------------------------------------------------------
// Release-arrive / acquire-poll grid barrier primitives (no full membar).
// ---------------------------------------------------------------------------
__device__ __forceinline__ void bar_arrive_release(int* ctr) {
    asm volatile("red.release.gpu.global.add.u32 [%0], 1;" :: "l"(ctr) : "memory");
}
__device__ __forceinline__ int bar_load_acquire(int* ctr) {
    int v;
    asm volatile("ld.acquire.gpu.global.u32 %0, [%1];" : "=r"(v) : "l"(ctr) : "memory");
    return v;
}

// ---------------------------------------------------------------------------
// Prologue A: Wc = fp16(W_ih + W_hh) with column permutation
//   uint4 t = r*256 + i*32 + lane ; half j inside it holds column
//   c = lane + 256*i + 32*j  -> per-lane h gathers are bank-conflict-free.
// ---------------------------------------------------------------------------
__global__ void lstm_prologue(const float* __restrict__ W_ih,
                              const float* __restrict__ W_hh,
                              const float* __restrict__ b_ih,
                              const float* __restrict__ b_hh) {
    const long long idx    = (long long)blockIdx.x * blockDim.x + threadIdx.x;
    const long long stride = (long long)gridDim.x * blockDim.x;
    const long long TOT    = (long long)4 * H * 8 * 32;   // rows * i * lane
    for (long long t = idx; t < TOT; t += stride) {
        const int l = (int)(t & 31);
        const int i = (int)((t >> 5) & 7);
        const int r = (int)(t >> 8);
        const float* wi = W_ih + (size_t)r * H;
        const float* wh = W_hh + (size_t)r * H;
        __half hv[8];
        #pragma unroll
        for (int j = 0; j < 8; j++) {
            const int c = l + 256 * i + 32 * j;
            hv[j] = __float2half(wi[c] + wh[c]);
        }
        ((uint4*)g_Wh)[t] = *(const uint4*)hv;
    }
    if (idx < 4 * H) g_bc[idx] = b_ih[idx] + b_hh[idx];
    if (idx == 0)    g_ctr = 0;
}

// ---------------------------------------------------------------------------
// Prologue B: exact fp32 step-0 gates:  gates0 = W_ih @ x0 + b_ih + b_hh
// ---------------------------------------------------------------------------
__global__ void lstm_gates0(const float* __restrict__ inputs,
                            const float* __restrict__ W_ih,
                            const float* __restrict__ b_ih,
                            const float* __restrict__ b_hh) {
    const int row  = blockIdx.x * 8 + (threadIdx.x >> 5);
    const int lane = threadIdx.x & 31;
    if (row >= 4 * H) return;
    const float4* w4 = (const float4*)(W_ih + (size_t)row * H);
    const float4* x4 = (const float4*)inputs;   // row 0 of inputs
    float acc = 0.0f;
    for (int c = lane; c < H / 4; c += 32) {
        float4 w = __ldg(w4 + c), x = __ldg(x4 + c);
        acc = fmaf(w.x, x.x, acc);
        acc = fmaf(w.y, x.y, acc);
        acc = fmaf(w.z, x.z, acc);
        acc = fmaf(w.w, x.w, acc);
    }
    #pragma unroll
    for (int o = 16; o; o >>= 1) acc += __shfl_xor_sync(0xffffffffu, acc, o);
    if (lane == 0) g_gates0[row] = acc + b_ih[row] + b_hh[row];
}

__device__ __forceinline__ float sigmoidf_fast(float x) {
    return 1.0f / (1.0f + __expf(-x));
}

// Dot of one permuted fp16 weight row with the register-resident h slice.
template <bool GLOBAL>
__device__ __forceinline__ float row_dot(const uint4* __restrict__ wr,
                                         const float (&hreg)[8][8], int lane) {
    float a0 = 0.f, a1 = 0.f, a2 = 0.f, a3 = 0.f;
    #pragma unroll
    for (int i = 0; i < 8; i++) {
        uint4 w = GLOBAL ? __ldg(wr + lane + 32 * i) : wr[lane + 32 * i];
        const __half2* wh = reinterpret_cast<const __half2*>(&w);
        const float2 f0 = __half22float2(wh[0]);
        const float2 f1 = __half22float2(wh[1]);
        const float2 f2 = __half22float2(wh[2]);
        const float2 f3 = __half22float2(wh[3]);
        a0 = fmaf(f0.x, hreg[i][0], a0);
        a1 = fmaf(f0.y, hreg[i][1], a1);
        a2 = fmaf(f1.x, hreg[i][2], a2);
        a3 = fmaf(f1.y, hreg[i][3], a3);
        a0 = fmaf(f2.x, hreg[i][4], a0);
        a1 = fmaf(f2.y, hreg[i][5], a1);
        a2 = fmaf(f3.x, hreg[i][6], a2);
        a3 = fmaf(f3.y, hreg[i][7], a3);
    }
    return (a0 + a1) + (a2 + a3);
}

// ---------------------------------------------------------------------------
// Persistent LSTM: weights live in SMEM (fp16), h in registers, fp32 accum.
// ---------------------------------------------------------------------------
__global__ void __launch_bounds__(NTHREADS, 1)
lstm_main(const float* __restrict__ W_out,
          const float* __restrict__ b_out,
          const int*   __restrict__ steps_ptr,
          float*       __restrict__ out) {
    extern __shared__ unsigned char smem_raw[];
    __half* sh_w = (__half*)smem_raw;
    float*  sh_h = (float*)(smem_raw + SMEM_W_BYTES);
    __shared__ float sh_g[128];
    __shared__ float sh_b[128];
    __shared__ float sh_c[64];
    __shared__ float sh_logits[16];

    const int tid  = threadIdx.x;
    const int warp = tid >> 5;
    const int lane = tid & 31;
    const int nb   = gridDim.x;
    const int bid  = blockIdx.x;

    const int k0 = (int)(((long long)bid * H) / nb);
    const int k1 = (int)(((long long)(bid + 1) * H) / nb);
    const int nk = k1 - k0;
    const int nrows = nk * 4;
    const int cached = nrows < CACHED_ROWS ? nrows : CACHED_ROWS;
    const int steps = steps_ptr ? steps_ptr[0] : 512;

    // --- one-time prefill: cached weight rows, biases, cell state ---
    {
        const uint4* gW4 = (const uint4*)g_Wh;
        uint4* sW4 = (uint4*)sh_w;
        const int tot = cached * (H / 8);              // 256 uint4 per row
        for (int idx = tid; idx < tot; idx += NTHREADS) {
            const int lr  = idx >> 8;
            const int pos = idx & 255;
            const int grow = (lr & 3) * H + k0 + (lr >> 2);
            sW4[lr * 256 + pos] = __ldg(gW4 + (size_t)grow * 256 + pos);
        }
        if (tid < nrows) sh_b[tid] = g_bc[(tid & 3) * H + k0 + (tid >> 2)];
        for (int k = tid; k < nk; k += NTHREADS) sh_c[k] = 0.0f;
    }
    __syncthreads();

    for (int s = 0; s < steps; ++s) {
        if (s == 0) {
            if (tid < nrows)
                sh_g[tid] = g_gates0[(tid & 3) * H + k0 + (tid >> 2)];
            __syncthreads();
        } else {
            // stage h (written by all blocks last step) into smem, L1-bypassing
            const float4* hin4 = (const float4*)g_hbuf[s & 1];
            for (int i = tid; i < H / 4; i += NTHREADS)
                ((float4*)sh_h)[i] = __ldcg(hin4 + i);
            __syncthreads();

            // per-lane h slice -> registers (conflict-free: bank == lane)
            float hreg[8][8];
            #pragma unroll
            for (int i = 0; i < 8; i++)
                #pragma unroll
                for (int j = 0; j < 8; j++)
                    hreg[i][j] = sh_h[lane + 256 * i + 32 * j];

            for (int r = warp; r < nrows; r += NTHREADS / 32) {
                float acc;
                if (r < cached) {
                    acc = row_dot<false>((const uint4*)(sh_w + (size_t)r * H), hreg, lane);
                } else {
                    const size_t grow = (size_t)((r & 3) * H + k0 + (r >> 2));
                    acc = row_dot<true>(((const uint4*)g_Wh) + grow * (H / 8), hreg, lane);
                }
                #pragma unroll
                for (int o = 16; o; o >>= 1)
                    acc += __shfl_xor_sync(0xffffffffu, acc, o);
                if (lane == 0) sh_g[r] = acc + sh_b[r];
            }
            __syncthreads();
        }

        // elementwise LSTM update (block-local)
        float* hout = g_hbuf[(s + 1) & 1];
        for (int k = tid; k < nk; k += NTHREADS) {
            const float i_g = sigmoidf_fast(sh_g[k * 4 + 0]);
            const float f_g = sigmoidf_fast(sh_g[k * 4 + 1]);
            const float g_g = tanhf(sh_g[k * 4 + 2]);
            const float o_g = sigmoidf_fast(sh_g[k * 4 + 3]);
            const float c_n = f_g * sh_c[k] + i_g * g_g;
            sh_c[k] = c_n;
            const float h_n = o_g * tanhf(c_n);
            hout[k0 + k] = h_n;
            if (s == steps - 1) {
                out[11 + k0 + k]     = h_n;
                out[11 + H + k0 + k] = c_n;
            }
        }

        // grid barrier: release-arrive, acquire-poll (no membar, no nanosleep)
        __syncthreads();
        if (tid == 0) {
            bar_arrive_release(&g_ctr);
            const int target = nb * (s + 1);
            while (bar_load_acquire(&g_ctr) < target) { }
        }
        __syncthreads();
    }

    // classification head + softmax (block 0)
    if (bid == 0) {
        const float4* hf4 = (const float4*)g_hbuf[steps & 1];
        for (int i = tid; i < H / 4; i += NTHREADS)
            ((float4*)sh_h)[i] = __ldcg(hf4 + i);
        __syncthreads();
        for (int r = warp; r < 11; r += NTHREADS / 32) {
            const float4* wrow = (const float4*)(W_out + (size_t)r * H);
            float acc = 0.0f;
            for (int c = lane; c < H / 4; c += 32) {
                float4 w  = __ldg(wrow + c);
                float4 hv = ((float4*)sh_h)[c];
                acc = fmaf(w.x, hv.x, acc);
                acc = fmaf(w.y, hv.y, acc);
                acc = fmaf(w.z, hv.z, acc);
                acc = fmaf(w.w, hv.w, acc);
            }
            #pragma unroll
            for (int o = 16; o; o >>= 1)
                acc += __shfl_xor_sync(0xffffffffu, acc, o);
            if (lane == 0) sh_logits[r] = acc + __ldg(b_out + r);
        }
        __syncthreads();
        if (tid == 0) {
            float m = sh_logits[0];
            #pragma unroll
            for (int i = 1; i < 11; i++) m = fmaxf(m, sh_logits[i]);
            float e[11], sum = 0.0f;
            #pragma unroll
            for (int i = 0; i < 11; i++) { e[i] = __expf(sh_logits[i] - m); sum += e[i]; }
            const float inv = 1.0f / sum;
            #pragma unroll
            for (int i = 0; i < 11; i++) out[i] = e[i] * inv;
        }
    }
}

// ---------------------------------------------------------------------------
extern "C" void kernel_launch(void* const* d_in, const int* in_sizes, int n_in,
                              void* d_out, int out_size) {
    const float* inputs = (const float*)d_in[0];
    const float* W_ih   = (const float*)d_in[1];
    const float* W_hh   = (const float*)d_in[2];
    const float* b_ih   = (const float*)d_in[3];
    const float* b_hh   = (const float*)d_in[4];
    const float* W_out  = (const float*)d_in[5];
    const float* b_out  = (const float*)d_in[6];
    const int*   steps  = (n_in > 7) ? (const int*)d_in[7] : nullptr;
    float* out = (float*)d_out;

    int nsm = 148;
    cudaDeviceGetAttribute(&nsm, cudaDevAttrMultiProcessorCount, 0);

    cudaFuncSetAttribute(lstm_main, cudaFuncAttributeMaxDynamicSharedMemorySize,
                         SMEM_DYN_BYTES);

    lstm_prologue<<<2048, 256>>>(W_ih, W_hh, b_ih, b_hh);
    lstm_gates0<<<1024, 256>>>(inputs, W_ih, b_ih, b_hh);
    lstm_main<<<nsm, NTHREADS, SMEM_DYN_BYTES>>>(W_out, b_out, steps, out);
}

// round 5
// speedup vs baseline: 1.8100x; 1.2326x over previous
#include <cuda_runtime.h>
#include <cuda_fp16.h>

#define H 2048
#define NTHREADS 512
#define CACHED_ROWS 52
#define SMEM_W_BYTES (CACHED_ROWS * H * 2)          // 212992 B fp16 weights
#define SMEM_HH_BYTES (H * 2)                       // 4096 B half2 hidden (1024 x half2)
#define SMEM_DYN_BYTES (SMEM_W_BYTES + SMEM_HH_BYTES)

// -------- persistent device scratch (static allocation is allowed) --------
__device__ __half g_Wh[4 * H * H];   // combined W_ih+W_hh, fp16, permuted, 32 MB
__device__ float  g_bc[4 * H];       // b_ih + b_hh
__device__ float  g_gates0[4 * H];   // exact fp32 gates of step 0
__device__ float  g_hbuf[2][H];      // double-buffered hidden state (fp32)
__device__ int    g_ctr;             // grid barrier counter

// ---------------------------------------------------------------------------
// Release-arrive / acquire-poll grid barrier primitives.
// ---------------------------------------------------------------------------
__device__ __forceinline__ void bar_arrive_release(int* ctr) {
    asm volatile("red.release.gpu.global.add.u32 [%0], 1;" :: "l"(ctr) : "memory");
}
__device__ __forceinline__ int bar_load_acquire(int* ctr) {
    int v;
    asm volatile("ld.acquire.gpu.global.u32 %0, [%1];" : "=r"(v) : "l"(ctr) : "memory");
    return v;
}

// ---------------------------------------------------------------------------
// Prologue A: Wc = fp16(W_ih + W_hh), permuted for half2 math.
//   uint4 t = r*256 + i*32 + lane holds 4 half2 slots j2=0..3.
//   Slot j2 covers columns (2q, 2q+1) with q = lane + 32*(4*i + j2),
//   matching the consumer's conflict-free h gather hh[lane + 32*m], m=4i+j2.
// ---------------------------------------------------------------------------
__global__ void lstm_prologue(const float* __restrict__ W_ih,
                              const float* __restrict__ W_hh,
                              const float* __restrict__ b_ih,
                              const float* __restrict__ b_hh) {
    const long long idx    = (long long)blockIdx.x * blockDim.x + threadIdx.x;
    const long long stride = (long long)gridDim.x * blockDim.x;
    const long long TOT    = (long long)4 * H * 8 * 32;   // rows * i * lane
    for (long long t = idx; t < TOT; t += stride) {
        const int l = (int)(t & 31);
        const int i = (int)((t >> 5) & 7);
        const int r = (int)(t >> 8);
        const float* wi = W_ih + (size_t)r * H;
        const float* wh = W_hh + (size_t)r * H;
        __half hv[8];
        #pragma unroll
        for (int j2 = 0; j2 < 4; j2++) {
            const int q  = l + 32 * (4 * i + j2);
            const int c0 = 2 * q;
            hv[2 * j2 + 0] = __float2half(wi[c0]     + wh[c0]);
            hv[2 * j2 + 1] = __float2half(wi[c0 + 1] + wh[c0 + 1]);
        }
        ((uint4*)g_Wh)[t] = *(const uint4*)hv;
    }
    if (idx < 4 * H) g_bc[idx] = b_ih[idx] + b_hh[idx];
    if (idx == 0)    g_ctr = 0;
}

// ---------------------------------------------------------------------------
// Prologue B: exact fp32 step-0 gates:  gates0 = W_ih @ x0 + b_ih + b_hh
// ---------------------------------------------------------------------------
__global__ void lstm_gates0(const float* __restrict__ inputs,
                            const float* __restrict__ W_ih,
                            const float* __restrict__ b_ih,
                            const float* __restrict__ b_hh) {
    const int row  = blockIdx.x * 8 + (threadIdx.x >> 5);
    const int lane = threadIdx.x & 31;
    if (row >= 4 * H) return;
    const float4* w4 = (const float4*)(W_ih + (size_t)row * H);
    const float4* x4 = (const float4*)inputs;   // row 0 of inputs
    float acc = 0.0f;
    for (int c = lane; c < H / 4; c += 32) {
        float4 w = __ldg(w4 + c), x = __ldg(x4 + c);
        acc = fmaf(w.x, x.x, acc);
        acc = fmaf(w.y, x.y, acc);
        acc = fmaf(w.z, x.z, acc);
        acc = fmaf(w.w, x.w, acc);
    }
    #pragma unroll
    for (int o = 16; o; o >>= 1) acc += __shfl_xor_sync(0xffffffffu, acc, o);
    if (lane == 0) g_gates0[row] = acc + b_ih[row] + b_hh[row];
}

__device__ __forceinline__ float sigmoidf_fast(float x) {
    return 1.0f / (1.0f + __expf(-x));
}

// Dot of one permuted fp16 weight row with the half2-register h slice.
// fp16 partial chains of 4 HFMA2 (8 scalar terms), widened to fp32 per chunk.
template <bool GLOBAL>
__device__ __forceinline__ float row_dot_h2(const uint4* __restrict__ wr,
                                            const __half2 (&hh)[32], int lane) {
    float acc0 = 0.f, acc1 = 0.f;
    #pragma unroll
    for (int i = 0; i < 8; i++) {
        uint4 w = GLOBAL ? __ldg(wr + lane + 32 * i) : wr[lane + 32 * i];
        const __half2* wh = reinterpret_cast<const __half2*>(&w);
        __half2 p = __hmul2(wh[0], hh[4 * i + 0]);
        p = __hfma2(wh[1], hh[4 * i + 1], p);
        p = __hfma2(wh[2], hh[4 * i + 2], p);
        p = __hfma2(wh[3], hh[4 * i + 3], p);
        const float2 f = __half22float2(p);
        acc0 += f.x;
        acc1 += f.y;
    }
    return acc0 + acc1;
}

// ---------------------------------------------------------------------------
// Persistent LSTM: fp16 weights in SMEM, h as half2 in regs, fp32 master accum.
// ---------------------------------------------------------------------------
__global__ void __launch_bounds__(NTHREADS, 1)
lstm_main(const float* __restrict__ W_out,
          const float* __restrict__ b_out,
          const int*   __restrict__ steps_ptr,
          float*       __restrict__ out) {
    extern __shared__ unsigned char smem_raw[];
    __half*  sh_w  = (__half*)smem_raw;
    __half2* sh_hh = (__half2*)(smem_raw + SMEM_W_BYTES);   // 1024 half2
    __shared__ float sh_g[128];
    __shared__ float sh_b[128];
    __shared__ float sh_c[64];
    __shared__ float sh_logits[16];

    const int tid  = threadIdx.x;
    const int warp = tid >> 5;
    const int lane = tid & 31;
    const int nb   = gridDim.x;
    const int bid  = blockIdx.x;

    const int k0 = (int)(((long long)bid * H) / nb);
    const int k1 = (int)(((long long)(bid + 1) * H) / nb);
    const int nk = k1 - k0;
    const int nrows = nk * 4;
    const int cached = nrows < CACHED_ROWS ? nrows : CACHED_ROWS;
    const int steps = steps_ptr ? steps_ptr[0] : 512;

    // --- one-time prefill: cached weight rows, biases, cell state ---
    {
        const uint4* gW4 = (const uint4*)g_Wh;
        uint4* sW4 = (uint4*)sh_w;
        const int tot = cached * (H / 8);              // 256 uint4 per row
        for (int idx = tid; idx < tot; idx += NTHREADS) {
            const int lr  = idx >> 8;
            const int pos = idx & 255;
            const int grow = (lr & 3) * H + k0 + (lr >> 2);
            sW4[lr * 256 + pos] = __ldg(gW4 + (size_t)grow * 256 + pos);
        }
        if (tid < nrows) sh_b[tid] = g_bc[(tid & 3) * H + k0 + (tid >> 2)];
        if (tid < nk) sh_c[tid] = 0.0f;
    }
    __syncthreads();

    for (int s = 0; s < steps; ++s) {
        if (s == 0) {
            if (tid < nrows)
                sh_g[tid] = g_gates0[(tid & 3) * H + k0 + (tid >> 2)];
            __syncthreads();
        } else {
            // stage h: fp32 from L2 (bypass L1), convert to half2 into smem
            const float2* hin2 = (const float2*)g_hbuf[s & 1];
            #pragma unroll
            for (int i = tid; i < H / 2; i += NTHREADS) {
                const float2 v = __ldcg(hin2 + i);
                sh_hh[i] = __floats2half2_rn(v.x, v.y);
            }
            __syncthreads();

            // per-lane half2 h slice -> registers (bank == lane, conflict-free)
            __half2 hreg[32];
            #pragma unroll
            for (int m = 0; m < 32; m++)
                hreg[m] = sh_hh[lane + 32 * m];

            for (int r = warp; r < nrows; r += NTHREADS / 32) {
                float acc;
                if (r < cached) {
                    acc = row_dot_h2<false>((const uint4*)(sh_w + (size_t)r * H), hreg, lane);
                } else {
                    const size_t grow = (size_t)((r & 3) * H + k0 + (r >> 2));
                    acc = row_dot_h2<true>(((const uint4*)g_Wh) + grow * (H / 8), hreg, lane);
                }
                #pragma unroll
                for (int o = 16; o; o >>= 1)
                    acc += __shfl_xor_sync(0xffffffffu, acc, o);
                if (lane == 0) sh_g[r] = acc + sh_b[r];
            }
            __syncthreads();
        }

        // elementwise LSTM update (block-local)
        float* hout = g_hbuf[(s + 1) & 1];
        if (tid < nk) {
            const float i_g = sigmoidf_fast(sh_g[tid * 4 + 0]);
            const float f_g = sigmoidf_fast(sh_g[tid * 4 + 1]);
            const float g_g = tanhf(sh_g[tid * 4 + 2]);
            const float o_g = sigmoidf_fast(sh_g[tid * 4 + 3]);
            const float c_n = f_g * sh_c[tid] + i_g * g_g;
            sh_c[tid] = c_n;
            const float h_n = o_g * tanhf(c_n);
            hout[k0 + tid] = h_n;
            if (s == steps - 1) {
                out[11 + k0 + tid]     = h_n;
                out[11 + H + k0 + tid] = c_n;
            }
        }

        // grid barrier: release-arrive, acquire-poll
        __syncthreads();
        if (tid == 0) {
            bar_arrive_release(&g_ctr);
            const int target = nb * (s + 1);
            while (bar_load_acquire(&g_ctr) < target) { }
        }
        __syncthreads();
    }

    // classification head + softmax (block 0); direct L2 reads of final h
    if (bid == 0) {
        const float4* hf4 = (const float4*)g_hbuf[steps & 1];
        for (int r = warp; r < 11; r += NTHREADS / 32) {
            const float4* wrow = (const float4*)(W_out + (size_t)r * H);
            float acc = 0.0f;
            for (int c = lane; c < H / 4; c += 32) {
                const float4 w  = __ldg(wrow + c);
                const float4 hv = __ldcg(hf4 + c);
                acc = fmaf(w.x, hv.x, acc);
                acc = fmaf(w.y, hv.y, acc);
                acc = fmaf(w.z, hv.z, acc);
                acc = fmaf(w.w, hv.w, acc);
            }
            #pragma unroll
            for (int o = 16; o; o >>= 1)
                acc += __shfl_xor_sync(0xffffffffu, acc, o);
            if (lane == 0) sh_logits[r] = acc + __ldg(b_out + r);
        }
        __syncthreads();
        if (tid == 0) {
            float m = sh_logits[0];
            #pragma unroll
            for (int i = 1; i < 11; i++) m = fmaxf(m, sh_logits[i]);
            float e[11], sum = 0.0f;
            #pragma unroll
            for (int i = 0; i < 11; i++) { e[i] = __expf(sh_logits[i] - m); sum += e[i]; }
            const float inv = 1.0f / sum;
            #pragma unroll
            for (int i = 0; i < 11; i++) out[i] = e[i] * inv;
        }
    }
}

// ---------------------------------------------------------------------------
extern "C" void kernel_launch(void* const* d_in, const int* in_sizes, int n_in,
                              void* d_out, int out_size) {
    const float* inputs = (const float*)d_in[0];
    const float* W_ih   = (const float*)d_in[1];
    const float* W_hh   = (const float*)d_in[2];
    const float* b_ih   = (const float*)d_in[3];
    const float* b_hh   = (const float*)d_in[4];
    const float* W_out  = (const float*)d_in[5];
    const float* b_out  = (const float*)d_in[6];
    const int*   steps  = (n_in > 7) ? (const int*)d_in[7] : nullptr;
    float* out = (float*)d_out;

    int nsm = 148;
    cudaDeviceGetAttribute(&nsm, cudaDevAttrMultiProcessorCount, 0);

    cudaFuncSetAttribute(lstm_main, cudaFuncAttributeMaxDynamicSharedMemorySize,
                         SMEM_DYN_BYTES);

    lstm_prologue<<<2048, 256>>>(W_ih, W_hh, b_ih, b_hh);
    lstm_gates0<<<1024, 256>>>(inputs, W_ih, b_ih, b_hh);
    lstm_main<<<nsm, NTHREADS, SMEM_DYN_BYTES>>>(W_out, b_out, steps, out);
}